// round 3
// baseline (speedup 1.0000x reference)
#include <cuda_runtime.h>

// Problem constants (fixed by the dataset)
#define TILE_P 128
#define SSEG   16384   // B*D = 256*64
#define FDIM   64

// Segment accumulation tables (scratch; __device__ globals, no allocs)
__device__ float g_seg_t[SSEG * 32];
__device__ float g_seg_r[SSEG * 32];

__global__ void zero_seg_kernel() {
    int i = blockIdx.x * blockDim.x + threadIdx.x;
    if (i < SSEG * 32) { g_seg_t[i] = 0.f; g_seg_r[i] = 0.f; }
}

// ---- dynamic smem layout (float offsets) for the main kernel ----
#define OFF_XT   0        // x transposed: [64][128]
#define OFF_W0   8192     // layer1 weights [64][128]
#define OFF_W1   16384    // layer2 weights [128][32]
#define OFF_H1T  20480    // hidden transposed [128][132]  (pad stride 132)
#define OFF_H2T  37376    // table branch out [128][32]
#define OFF_H2R  41472    // rl branch out [128][32]
#define OFF_B0   45568    // layer1 bias [128]
#define OFF_B1   45696    // layer2 bias [32]
#define OFF_SID  45728    // segment ids [128] (ints)
#define SMEM_FLOATS 45856
#define SMEM_BYTES  (SMEM_FLOATS * 4)

__device__ __forceinline__ void copy4(float* dst, const float* __restrict__ src,
                                      int n, int tid) {
    for (int i = tid; i < (n >> 2); i += 256)
        reinterpret_cast<float4*>(dst)[i] =
            reinterpret_cast<const float4*>(src)[i];
}

// One branch: GEMM1 [128x64]@[64x128] -> relu -> h1T, GEMM2 [128x128]@[128x32] -> relu -> h2
__device__ __forceinline__ void run_branch(float* sm, int tx, int ty, int h2off) {
    // ---------------- GEMM1 ----------------
    float acc[8][8];
#pragma unroll
    for (int ji = 0; ji < 8; ji++) {
        float b = sm[OFF_B0 + tx + 16 * ji];
#pragma unroll
        for (int pi = 0; pi < 8; pi++) acc[pi][ji] = b;
    }
#pragma unroll 4
    for (int k = 0; k < 64; k++) {
        float a[8], w[8];
        float4 v0 = *reinterpret_cast<const float4*>(&sm[OFF_XT + k * 128 + ty * 8]);
        float4 v1 = *reinterpret_cast<const float4*>(&sm[OFF_XT + k * 128 + ty * 8 + 4]);
        a[0] = v0.x; a[1] = v0.y; a[2] = v0.z; a[3] = v0.w;
        a[4] = v1.x; a[5] = v1.y; a[6] = v1.z; a[7] = v1.w;
#pragma unroll
        for (int ji = 0; ji < 8; ji++) w[ji] = sm[OFF_W0 + k * 128 + tx + 16 * ji];
#pragma unroll
        for (int pi = 0; pi < 8; pi++)
#pragma unroll
            for (int ji = 0; ji < 8; ji++)
                acc[pi][ji] = fmaf(a[pi], w[ji], acc[pi][ji]);
    }
    // relu + store transposed, conflict-free (j = tx + 16*ji, stride 132)
#pragma unroll
    for (int ji = 0; ji < 8; ji++) {
        int j = tx + 16 * ji;
        float4 v0, v1;
        v0.x = fmaxf(acc[0][ji], 0.f); v0.y = fmaxf(acc[1][ji], 0.f);
        v0.z = fmaxf(acc[2][ji], 0.f); v0.w = fmaxf(acc[3][ji], 0.f);
        v1.x = fmaxf(acc[4][ji], 0.f); v1.y = fmaxf(acc[5][ji], 0.f);
        v1.z = fmaxf(acc[6][ji], 0.f); v1.w = fmaxf(acc[7][ji], 0.f);
        *reinterpret_cast<float4*>(&sm[OFF_H1T + j * 132 + ty * 8])     = v0;
        *reinterpret_cast<float4*>(&sm[OFF_H1T + j * 132 + ty * 8 + 4]) = v1;
    }
    __syncthreads();
    // ---------------- GEMM2 ----------------
    float acc2[8][2];
    {
        float b0 = sm[OFF_B1 + tx * 2];
        float b1 = sm[OFF_B1 + tx * 2 + 1];
#pragma unroll
        for (int pi = 0; pi < 8; pi++) { acc2[pi][0] = b0; acc2[pi][1] = b1; }
    }
#pragma unroll 4
    for (int j = 0; j < 128; j++) {
        float4 a0 = *reinterpret_cast<const float4*>(&sm[OFF_H1T + j * 132 + ty * 8]);
        float4 a1 = *reinterpret_cast<const float4*>(&sm[OFF_H1T + j * 132 + ty * 8 + 4]);
        float2 w  = *reinterpret_cast<const float2*>(&sm[OFF_W1 + j * 32 + tx * 2]);
        float a[8] = {a0.x, a0.y, a0.z, a0.w, a1.x, a1.y, a1.z, a1.w};
#pragma unroll
        for (int pi = 0; pi < 8; pi++) {
            acc2[pi][0] = fmaf(a[pi], w.x, acc2[pi][0]);
            acc2[pi][1] = fmaf(a[pi], w.y, acc2[pi][1]);
        }
    }
#pragma unroll
    for (int pi = 0; pi < 8; pi++) {
        float2 o;
        o.x = fmaxf(acc2[pi][0], 0.f);
        o.y = fmaxf(acc2[pi][1], 0.f);
        *reinterpret_cast<float2*>(&sm[h2off + (ty * 8 + pi) * 32 + tx * 2]) = o;
    }
}

__global__ __launch_bounds__(256, 1)
void fused_mlp_seg_kernel(const float* __restrict__ x, const int* __restrict__ seg,
                          const float* __restrict__ w0t, const float* __restrict__ b0t,
                          const float* __restrict__ w1t, const float* __restrict__ b1t,
                          const float* __restrict__ w0r, const float* __restrict__ b0r,
                          const float* __restrict__ w1r, const float* __restrict__ b1r,
                          int N) {
    extern __shared__ float sm[];
    int tid = threadIdx.x;
    int p0  = blockIdx.x * TILE_P;
    int tx  = tid & 15, ty = tid >> 4;

    // load x tile transposed (xT[k][p]); pad tail points with 0, sid=-1
    {
        const float4* x4 = reinterpret_cast<const float4*>(x);
#pragma unroll
        for (int it = 0; it < 8; ++it) {
            int idx = tid + it * 256;          // 0..2047
            int p = idx >> 4, c4 = idx & 15;
            float4 v = make_float4(0.f, 0.f, 0.f, 0.f);
            if (p0 + p < N) v = x4[(size_t)(p0 + p) * 16 + c4];
            sm[OFF_XT + (c4 * 4 + 0) * 128 + p] = v.x;
            sm[OFF_XT + (c4 * 4 + 1) * 128 + p] = v.y;
            sm[OFF_XT + (c4 * 4 + 2) * 128 + p] = v.z;
            sm[OFF_XT + (c4 * 4 + 3) * 128 + p] = v.w;
        }
        if (tid < TILE_P)
            reinterpret_cast<int*>(sm)[OFF_SID + tid] =
                (p0 + tid < N) ? seg[p0 + tid] : -1;
    }
    // table-branch weights
    copy4(sm + OFF_W0, w0t, 8192, tid);
    copy4(sm + OFF_W1, w1t, 4096, tid);
    copy4(sm + OFF_B0, b0t, 128, tid);
    copy4(sm + OFF_B1, b1t, 32, tid);
    __syncthreads();

    run_branch(sm, tx, ty, OFF_H2T);
    __syncthreads();

    // swap in rl-branch weights (same slots)
    copy4(sm + OFF_W0, w0r, 8192, tid);
    copy4(sm + OFF_W1, w1r, 4096, tid);
    copy4(sm + OFF_B0, b0r, 128, tid);
    copy4(sm + OFF_B1, b1r, 32, tid);
    __syncthreads();

    run_branch(sm, tx, ty, OFF_H2R);
    __syncthreads();

    // ---- sorted-run segment reduction: 64 features x 4 point-chunks ----
    {
        int f  = tid & 63;           // 0..31 table, 32..63 rl
        int q  = tid >> 6;           // chunk 0..3 (32 points each)
        int fc = f & 31;
        const float* src = sm + ((f < 32) ? OFF_H2T : OFF_H2R);
        float* dst = (f < 32) ? g_seg_t : g_seg_r;
        const int* sid = reinterpret_cast<const int*>(sm) + OFF_SID;
        int cur = -1; float acc = 0.f;
#pragma unroll 1
        for (int p = q * 32; p < q * 32 + 32; ++p) {
            int s = sid[p];
            if (s != cur) {
                if (cur >= 0) atomicAdd(&dst[cur * 32 + fc], acc);
                cur = s; acc = 0.f;
            }
            if (s >= 0) acc += src[p * 32 + fc];
        }
        if (cur >= 0) atomicAdd(&dst[cur * 32 + fc], acc);
    }
}

// ---- per-segment heads + cost MLP + policy ----
// smem float offsets
#define HS_F0   0      // fwd0_w 2048
#define HS_C0   2048   // com0_w 2048
#define HS_B0   4096   // bwd0_w 2048
#define HS_CT1  6144   // cost1_w 2048
#define HS_F0B  8192
#define HS_C0B  8256
#define HS_B0B  8320
#define HS_F1   8384
#define HS_C1   8448
#define HS_B1   8512
#define HS_CT0  8576   // cost0_w 192
#define HS_CT0B 8768
#define HS_CT1B 8832
#define HS_POL  8864
#define HS_SCAL 8928   // fwd1_b, com1_b, bwd1_b, pol_b
#define HS_SIZE 8936

__global__ __launch_bounds__(256)
void head_kernel(const float* __restrict__ fwd0_w, const float* __restrict__ fwd0_b,
                 const float* __restrict__ fwd1_w, const float* __restrict__ fwd1_b,
                 const float* __restrict__ com0_w, const float* __restrict__ com0_b,
                 const float* __restrict__ com1_w, const float* __restrict__ com1_b,
                 const float* __restrict__ bwd0_w, const float* __restrict__ bwd0_b,
                 const float* __restrict__ bwd1_w, const float* __restrict__ bwd1_b,
                 const float* __restrict__ cost0_w, const float* __restrict__ cost0_b,
                 const float* __restrict__ cost1_w, const float* __restrict__ cost1_b,
                 const float* __restrict__ pol_w, const float* __restrict__ pol_b,
                 float* __restrict__ out) {
    __shared__ float sw[HS_SIZE];
    int tid = threadIdx.x;
    copy4(sw + HS_F0,   fwd0_w, 2048, tid);
    copy4(sw + HS_C0,   com0_w, 2048, tid);
    copy4(sw + HS_B0,   bwd0_w, 2048, tid);
    copy4(sw + HS_CT1,  cost1_w, 2048, tid);
    copy4(sw + HS_F0B,  fwd0_b, 64, tid);
    copy4(sw + HS_C0B,  com0_b, 64, tid);
    copy4(sw + HS_B0B,  bwd0_b, 64, tid);
    copy4(sw + HS_F1,   fwd1_w, 64, tid);
    copy4(sw + HS_C1,   com1_w, 64, tid);
    copy4(sw + HS_B1,   bwd1_w, 64, tid);
    copy4(sw + HS_CT0,  cost0_w, 192, tid);
    copy4(sw + HS_CT0B, cost0_b, 64, tid);
    copy4(sw + HS_CT1B, cost1_b, 32, tid);
    copy4(sw + HS_POL,  pol_w, 64, tid);
    if (tid == 0) {
        sw[HS_SCAL + 0] = fwd1_b[0];
        sw[HS_SCAL + 1] = com1_b[0];
        sw[HS_SCAL + 2] = bwd1_b[0];
        sw[HS_SCAL + 3] = pol_b[0];
    }
    __syncthreads();

    int s = blockIdx.x * 256 + tid;   // grid covers SSEG exactly

    float t[32], r[32];
#pragma unroll
    for (int i = 0; i < 8; i++) {
        float4 v = *reinterpret_cast<const float4*>(&g_seg_t[(size_t)s * 32 + i * 4]);
        t[i * 4] = v.x; t[i * 4 + 1] = v.y; t[i * 4 + 2] = v.z; t[i * 4 + 3] = v.w;
        float4 u = *reinterpret_cast<const float4*>(&g_seg_r[(size_t)s * 32 + i * 4]);
        r[i * 4] = u.x; r[i * 4 + 1] = u.y; r[i * 4 + 2] = u.z; r[i * 4 + 3] = u.w;
    }

    auto head = [&](const float* w0, const float* b0, const float* w1, float b1s) -> float {
        float o = b1s;
#pragma unroll
        for (int i4 = 0; i4 < 16; i4++) {
            float4 hb = *reinterpret_cast<const float4*>(&b0[i4 * 4]);
            float h0 = hb.x, h1 = hb.y, h2 = hb.z, h3 = hb.w;
#pragma unroll
            for (int k = 0; k < 32; k++) {
                float4 w = *reinterpret_cast<const float4*>(&w0[k * 64 + i4 * 4]);
                h0 = fmaf(t[k], w.x, h0); h1 = fmaf(t[k], w.y, h1);
                h2 = fmaf(t[k], w.z, h2); h3 = fmaf(t[k], w.w, h3);
            }
            float4 wv = *reinterpret_cast<const float4*>(&w1[i4 * 4]);
            o += fmaxf(h0, 0.f) * wv.x + fmaxf(h1, 0.f) * wv.y +
                 fmaxf(h2, 0.f) * wv.z + fmaxf(h3, 0.f) * wv.w;
        }
        return o;
    };

    float fc = head(sw + HS_F0, sw + HS_F0B, sw + HS_F1, sw[HS_SCAL + 0]);
    float cc = head(sw + HS_C0, sw + HS_C0B, sw + HS_C1, sw[HS_SCAL + 1]);
    float bc = head(sw + HS_B0, sw + HS_B0B, sw + HS_B1, sw[HS_SCAL + 2]);

    // cost MLP: [fc,cc,bc] -> 64 relu -> 32 relu; fuse layer2 outputs into policy dot
    float c1[64];
#pragma unroll
    for (int i4 = 0; i4 < 16; i4++) {
        float4 a  = *reinterpret_cast<const float4*>(&sw[HS_CT0B + i4 * 4]);
        float4 w0 = *reinterpret_cast<const float4*>(&sw[HS_CT0 + 0 * 64 + i4 * 4]);
        float4 w1 = *reinterpret_cast<const float4*>(&sw[HS_CT0 + 1 * 64 + i4 * 4]);
        float4 w2 = *reinterpret_cast<const float4*>(&sw[HS_CT0 + 2 * 64 + i4 * 4]);
        a.x = fmaf(fc, w0.x, fmaf(cc, w1.x, fmaf(bc, w2.x, a.x)));
        a.y = fmaf(fc, w0.y, fmaf(cc, w1.y, fmaf(bc, w2.y, a.y)));
        a.z = fmaf(fc, w0.z, fmaf(cc, w1.z, fmaf(bc, w2.z, a.z)));
        a.w = fmaf(fc, w0.w, fmaf(cc, w1.w, fmaf(bc, w2.w, a.w)));
        c1[i4 * 4 + 0] = fmaxf(a.x, 0.f);
        c1[i4 * 4 + 1] = fmaxf(a.y, 0.f);
        c1[i4 * 4 + 2] = fmaxf(a.z, 0.f);
        c1[i4 * 4 + 3] = fmaxf(a.w, 0.f);
    }

    float logit = sw[HS_SCAL + 3];
#pragma unroll
    for (int k = 0; k < 32; k++) logit = fmaf(r[k], sw[HS_POL + k], logit);

#pragma unroll
    for (int j4 = 0; j4 < 8; j4++) {
        float4 a = *reinterpret_cast<const float4*>(&sw[HS_CT1B + j4 * 4]);
#pragma unroll
        for (int k = 0; k < 64; k++) {
            float4 w = *reinterpret_cast<const float4*>(&sw[HS_CT1 + k * 32 + j4 * 4]);
            a.x = fmaf(c1[k], w.x, a.x); a.y = fmaf(c1[k], w.y, a.y);
            a.z = fmaf(c1[k], w.z, a.z); a.w = fmaf(c1[k], w.w, a.w);
        }
        float4 pw = *reinterpret_cast<const float4*>(&sw[HS_POL + 32 + j4 * 4]);
        logit += fmaxf(a.x, 0.f) * pw.x + fmaxf(a.y, 0.f) * pw.y +
                 fmaxf(a.z, 0.f) * pw.z + fmaxf(a.w, 0.f) * pw.w;
    }
    out[s] = logit;
}

extern "C" void kernel_launch(void* const* d_in, const int* in_sizes, int n_in,
                              void* d_out, int out_size) {
    // Inputs in setup_inputs order; B/D scalar inputs may or may not be present.
    int off = (in_sizes[2] == 1 && in_sizes[3] == 1) ? 4 : 2;
    const float* x   = (const float*)d_in[0];
    const int*   seg = (const int*)d_in[1];
    const float* tfc0_w = (const float*)d_in[off + 0];
    const float* tfc0_b = (const float*)d_in[off + 1];
    const float* tfc1_w = (const float*)d_in[off + 2];
    const float* tfc1_b = (const float*)d_in[off + 3];
    const float* fwd0_w = (const float*)d_in[off + 4];
    const float* fwd0_b = (const float*)d_in[off + 5];
    const float* fwd1_w = (const float*)d_in[off + 6];
    const float* fwd1_b = (const float*)d_in[off + 7];
    const float* com0_w = (const float*)d_in[off + 8];
    const float* com0_b = (const float*)d_in[off + 9];
    const float* com1_w = (const float*)d_in[off + 10];
    const float* com1_b = (const float*)d_in[off + 11];
    const float* bwd0_w = (const float*)d_in[off + 12];
    const float* bwd0_b = (const float*)d_in[off + 13];
    const float* bwd1_w = (const float*)d_in[off + 14];
    const float* bwd1_b = (const float*)d_in[off + 15];
    const float* rl0_w  = (const float*)d_in[off + 16];
    const float* rl0_b  = (const float*)d_in[off + 17];
    const float* rl1_w  = (const float*)d_in[off + 18];
    const float* rl1_b  = (const float*)d_in[off + 19];
    const float* cost0_w = (const float*)d_in[off + 20];
    const float* cost0_b = (const float*)d_in[off + 21];
    const float* cost1_w = (const float*)d_in[off + 22];
    const float* cost1_b = (const float*)d_in[off + 23];
    const float* pol_w   = (const float*)d_in[off + 24];
    const float* pol_b   = (const float*)d_in[off + 25];

    int N = in_sizes[0] / FDIM;

    cudaFuncSetAttribute(fused_mlp_seg_kernel,
                         cudaFuncAttributeMaxDynamicSharedMemorySize, SMEM_BYTES);

    zero_seg_kernel<<<(SSEG * 32 + 255) / 256, 256>>>();

    int grid = (N + TILE_P - 1) / TILE_P;
    fused_mlp_seg_kernel<<<grid, 256, SMEM_BYTES>>>(
        x, seg, tfc0_w, tfc0_b, tfc1_w, tfc1_b,
        rl0_w, rl0_b, rl1_w, rl1_b, N);

    head_kernel<<<SSEG / 256, 256>>>(
        fwd0_w, fwd0_b, fwd1_w, fwd1_b,
        com0_w, com0_b, com1_w, com1_b,
        bwd0_w, bwd0_b, bwd1_w, bwd1_b,
        cost0_w, cost0_b, cost1_w, cost1_b,
        pol_w, pol_b, (float*)d_out);
}

// round 8
// speedup vs baseline: 2.3358x; 2.3358x over previous
#include <cuda_runtime.h>
#include <cuda_bf16.h>
#include <cstdint>

// ============================ problem constants ============================
#define TILE_P 128
#define SSEG   16384          // B*D = 256*64
#define FDIM   64
#define NTHREADS 256
#define GRID_MAIN 148

// ============================ scratch globals ==============================
__device__ float g_seg_t[SSEG * 32];
__device__ float g_seg_r[SSEG * 32];
// pre-split, pre-swizzled bf16 weights: [branch][hi/lo]
__device__ unsigned char g_w0[2][2][16384];   // [64 k][128 n] bf16, 256B rows, SWZ
__device__ unsigned char g_w1[2][2][8192];    // [128 k][32 n] bf16,  64B rows, SWZ

#define SWZ(o) ((o) ^ ((((uint32_t)(o)) >> 3) & 0x70))

// ============================ smem layout (bytes) ==========================
#define SM_XH   0              // x tile hi: [128 p][64 k] bf16, 128B rows, SWZ
#define SM_XL   16384          // x tile lo
#define SM_W0   32768          // + br*32768 + h*16384
#define SM_W1   98304          // + br*16384 + h*8192
#define SM_H1H  131072         // H1 hi: [128 p][128 j] bf16, 256B rows, SWZ
#define SM_H1L  163840         // H1 lo
#define SM_H2   196608         // + br*16384 : [128 p][32] fp32
#define SM_SID  229376         // int[128]
#define SM_B0   229888         // float[2][128]
#define SM_B1   230912         // float[2][32]
#define SMEM_BYTES 231168

// ============================ PTX helpers ==================================
__device__ __forceinline__ uint32_t smem_u32(const void* p) {
    uint32_t a;
    asm("{ .reg .u64 t; cvta.to.shared.u64 t, %1; cvt.u32.u64 %0, t; }"
        : "=r"(a) : "l"(p));
    return a;
}
__device__ __forceinline__ void ldsm_x4(uint32_t* r, uint32_t a) {
    asm volatile("ldmatrix.sync.aligned.m8n8.x4.shared.b16 {%0,%1,%2,%3}, [%4];"
                 : "=r"(r[0]), "=r"(r[1]), "=r"(r[2]), "=r"(r[3]) : "r"(a));
}
__device__ __forceinline__ void ldsm_x2t(uint32_t& r0, uint32_t& r1, uint32_t a) {
    asm volatile("ldmatrix.sync.aligned.m8n8.x2.trans.shared.b16 {%0,%1}, [%2];"
                 : "=r"(r0), "=r"(r1) : "r"(a));
}
__device__ __forceinline__ void ldsm_x4t(uint32_t* r, uint32_t a) {
    asm volatile("ldmatrix.sync.aligned.m8n8.x4.trans.shared.b16 {%0,%1,%2,%3}, [%4];"
                 : "=r"(r[0]), "=r"(r[1]), "=r"(r[2]), "=r"(r[3]) : "r"(a));
}
__device__ __forceinline__ void mma_bf16(float* d, const uint32_t* a,
                                         uint32_t b0, uint32_t b1) {
    asm volatile(
        "mma.sync.aligned.m16n8k16.row.col.f32.bf16.bf16.f32 "
        "{%0,%1,%2,%3}, {%4,%5,%6,%7}, {%8,%9}, {%0,%1,%2,%3};"
        : "+f"(d[0]), "+f"(d[1]), "+f"(d[2]), "+f"(d[3])
        : "r"(a[0]), "r"(a[1]), "r"(a[2]), "r"(a[3]), "r"(b0), "r"(b1));
}

__device__ __forceinline__ uint32_t pack_bf2(__nv_bfloat16 a, __nv_bfloat16 b) {
    return (uint32_t)__bfloat16_as_ushort(a) |
           ((uint32_t)__bfloat16_as_ushort(b) << 16);
}
__device__ __forceinline__ void split2(float v0, float v1, uint32_t& hp, uint32_t& lp) {
    __nv_bfloat16 h0 = __float2bfloat16_rn(v0), h1 = __float2bfloat16_rn(v1);
    __nv_bfloat16 l0 = __float2bfloat16_rn(v0 - __bfloat162float(h0));
    __nv_bfloat16 l1 = __float2bfloat16_rn(v1 - __bfloat162float(h1));
    hp = pack_bf2(h0, h1);
    lp = pack_bf2(l0, l1);
}

// ============================ small kernels ================================
__global__ void zero_seg_kernel() {
    int i = blockIdx.x * blockDim.x + threadIdx.x;
    if (i < SSEG * 32) { g_seg_t[i] = 0.f; g_seg_r[i] = 0.f; }
}

__global__ void prep_kernel(const float* __restrict__ w0t, const float* __restrict__ w1t,
                            const float* __restrict__ w0r, const float* __restrict__ w1r) {
    int tid = threadIdx.x;
    const float* w0s[2] = {w0t, w0r};
    const float* w1s[2] = {w1t, w1r};
    for (int br = 0; br < 2; br++) {
        const float* w0 = w0s[br];
        for (int i = tid; i < 8192; i += NTHREADS) {    // [64 k][128 n]
            int k = i >> 7, n = i & 127;
            float v = w0[k * 128 + n];
            __nv_bfloat16 h = __float2bfloat16_rn(v);
            __nv_bfloat16 l = __float2bfloat16_rn(v - __bfloat162float(h));
            uint32_t off = SWZ((uint32_t)(k * 256 + n * 2));
            *(__nv_bfloat16*)(&g_w0[br][0][off]) = h;
            *(__nv_bfloat16*)(&g_w0[br][1][off]) = l;
        }
        const float* w1 = w1s[br];
        for (int i = tid; i < 4096; i += NTHREADS) {    // [128 k][32 n]
            int k = i >> 5, n = i & 31;
            float v = w1[k * 32 + n];
            __nv_bfloat16 h = __float2bfloat16_rn(v);
            __nv_bfloat16 l = __float2bfloat16_rn(v - __bfloat162float(h));
            uint32_t off = SWZ((uint32_t)(k * 64 + n * 2));
            *(__nv_bfloat16*)(&g_w1[br][0][off]) = h;
            *(__nv_bfloat16*)(&g_w1[br][1][off]) = l;
        }
    }
}

// ============================ main persistent kernel =======================
__global__ __launch_bounds__(NTHREADS, 1)
void mlp_mma_kernel(const float* __restrict__ x, const int* __restrict__ seg,
                    const float* __restrict__ b0t, const float* __restrict__ b0r,
                    const float* __restrict__ b1t, const float* __restrict__ b1r,
                    int N) {
    extern __shared__ char smem[];
    uint32_t sb = smem_u32(smem);
    int tid = threadIdx.x, lane = tid & 31, wid = tid >> 5;

    // stage weights (pre-split bf16, already swizzled) + biases
    {
        const uint4* s0 = reinterpret_cast<const uint4*>(&g_w0[0][0][0]);
        uint4* d0 = reinterpret_cast<uint4*>(smem + SM_W0);
        for (int i = tid; i < 65536 / 16; i += NTHREADS) d0[i] = s0[i];
        const uint4* s1 = reinterpret_cast<const uint4*>(&g_w1[0][0][0]);
        uint4* d1 = reinterpret_cast<uint4*>(smem + SM_W1);
        for (int i = tid; i < 32768 / 16; i += NTHREADS) d1[i] = s1[i];
        float* b0s = (float*)(smem + SM_B0);
        float* b1s = (float*)(smem + SM_B1);
        if (tid < 128) { b0s[tid] = b0t[tid]; b0s[128 + tid] = b0r[tid]; }
        if (tid < 32)  { b1s[tid] = b1t[tid]; b1s[32 + tid]  = b1r[tid]; }
    }
    __syncthreads();

    const float* b0s = (const float*)(smem + SM_B0);
    const float* b1s = (const float*)(smem + SM_B1);

    int T = (N + TILE_P - 1) / TILE_P;
    int tile = blockIdx.x;
    if (tile >= T) return;

    // ---- register prefetch of first tile ----
    float4 xr[8];
    int sidr = -1;
    {
        int p0 = tile * TILE_P;
        const float4* x4 = reinterpret_cast<const float4*>(x);
#pragma unroll
        for (int it = 0; it < 8; it++) {
            int idx = tid + it * NTHREADS;
            int p = idx >> 4, c4 = idx & 15;
            xr[it] = (p0 + p < N) ? x4[(size_t)(p0 + p) * 16 + c4]
                                  : make_float4(0.f, 0.f, 0.f, 0.f);
        }
        if (tid < TILE_P) sidr = (p0 + tid < N) ? seg[p0 + tid] : -1;
    }

    // ldmatrix lane-address components (shared by A frags of both GEMMs)
    const int am = (lane & 7) + ((lane >> 3) & 1) * 8;
    const int ak = (lane >> 4) * 16;

    for (; tile < T; tile += GRID_MAIN) {
        // ---- store prefetched x tile (split hi/lo) + sid ----
#pragma unroll
        for (int it = 0; it < 8; it++) {
            int idx = tid + it * NTHREADS;
            int p = idx >> 4, c4 = idx & 15;
            float4 v = xr[it];
            uint32_t h0, l0, h1, l1;
            split2(v.x, v.y, h0, l0);
            split2(v.z, v.w, h1, l1);
            uint32_t off = SWZ((uint32_t)(p * 128 + c4 * 8));
            *(uint2*)(smem + SM_XH + off) = make_uint2(h0, h1);
            *(uint2*)(smem + SM_XL + off) = make_uint2(l0, l1);
        }
        if (tid < TILE_P) ((int*)(smem + SM_SID))[tid] = sidr;
        __syncthreads();

        // ---- prefetch next tile into regs (overlaps all compute below) ----
        int nt = tile + GRID_MAIN;
        if (nt < T) {
            int p0 = nt * TILE_P;
            const float4* x4 = reinterpret_cast<const float4*>(x);
#pragma unroll
            for (int it = 0; it < 8; it++) {
                int idx = tid + it * NTHREADS;
                int p = idx >> 4, c4 = idx & 15;
                xr[it] = (p0 + p < N) ? x4[(size_t)(p0 + p) * 16 + c4]
                                      : make_float4(0.f, 0.f, 0.f, 0.f);
            }
            if (tid < TILE_P) sidr = (p0 + tid < N) ? seg[p0 + tid] : -1;
        }

#pragma unroll 1
        for (int br = 0; br < 2; br++) {
            // ================= GEMM1: [128p x 64k] @ W0 -> H1 =================
            // warp owns 16 N-cols [wid*16, wid*16+16), loops 8 M-blocks
            uint32_t Bh[2][4][2], Bl[2][4][2];
            {
                uint32_t w0h = sb + SM_W0 + br * 32768;
                uint32_t w0l = w0h + 16384;
                int tt = lane & 15;
#pragma unroll
                for (int ks = 0; ks < 4; ks++)
#pragma unroll
                    for (int nb = 0; nb < 2; nb++) {
                        uint32_t a = SWZ((uint32_t)((ks * 16 + tt) * 256 +
                                                    (wid * 16 + nb * 8) * 2));
                        ldsm_x2t(Bh[nb][ks][0], Bh[nb][ks][1], w0h + a);
                        ldsm_x2t(Bl[nb][ks][0], Bl[nb][ks][1], w0l + a);
                    }
            }
            float bj[2][2];
#pragma unroll
            for (int nb = 0; nb < 2; nb++) {
                int j0 = wid * 16 + nb * 8 + (lane & 3) * 2;
                bj[nb][0] = b0s[br * 128 + j0];
                bj[nb][1] = b0s[br * 128 + j0 + 1];
            }
#pragma unroll 1
            for (int mb = 0; mb < 8; mb++) {
                uint32_t Ah[4][4], Al[4][4];
#pragma unroll
                for (int ks = 0; ks < 4; ks++) {
                    uint32_t a = SWZ((uint32_t)((mb * 16 + am) * 128 + ks * 32 + ak));
                    ldsm_x4(Ah[ks], sb + SM_XH + a);
                    ldsm_x4(Al[ks], sb + SM_XL + a);
                }
                float d[2][4] = {{0.f, 0.f, 0.f, 0.f}, {0.f, 0.f, 0.f, 0.f}};
#pragma unroll
                for (int ks = 0; ks < 4; ks++)
#pragma unroll
                    for (int nb = 0; nb < 2; nb++) {
                        mma_bf16(d[nb], Ah[ks], Bh[nb][ks][0], Bh[nb][ks][1]);
                        mma_bf16(d[nb], Al[ks], Bh[nb][ks][0], Bh[nb][ks][1]);
                        mma_bf16(d[nb], Ah[ks], Bl[nb][ks][0], Bl[nb][ks][1]);
                    }
                // epilogue: bias + relu + split -> H1 hi/lo
                int pr = mb * 16 + (lane >> 2);
#pragma unroll
                for (int nb = 0; nb < 2; nb++) {
                    int j0 = wid * 16 + nb * 8 + (lane & 3) * 2;
                    uint32_t hp, lp;
                    split2(fmaxf(d[nb][0] + bj[nb][0], 0.f),
                           fmaxf(d[nb][1] + bj[nb][1], 0.f), hp, lp);
                    uint32_t o0 = SWZ((uint32_t)(pr * 256 + j0 * 2));
                    *(uint32_t*)(smem + SM_H1H + o0) = hp;
                    *(uint32_t*)(smem + SM_H1L + o0) = lp;
                    split2(fmaxf(d[nb][2] + bj[nb][0], 0.f),
                           fmaxf(d[nb][3] + bj[nb][1], 0.f), hp, lp);
                    uint32_t o1 = SWZ((uint32_t)((pr + 8) * 256 + j0 * 2));
                    *(uint32_t*)(smem + SM_H1H + o1) = hp;
                    *(uint32_t*)(smem + SM_H1L + o1) = lp;
                }
            }
            __syncthreads();

            // ================= GEMM2: [128p x 128k] @ W1 -> H2 ================
            // warp owns M-block wid (16 rows), full N=32
            float d2[4][4] = {{0.f, 0.f, 0.f, 0.f}, {0.f, 0.f, 0.f, 0.f},
                              {0.f, 0.f, 0.f, 0.f}, {0.f, 0.f, 0.f, 0.f}};
            {
                uint32_t w1h = sb + SM_W1 + br * 16384;
                uint32_t w1l = w1h + 8192;
                int bk = lane & 7, bnb = (lane >> 3) * 16;
#pragma unroll
                for (int ks = 0; ks < 8; ks++) {
                    uint32_t a = SWZ((uint32_t)((wid * 16 + am) * 256 + ks * 32 + ak));
                    uint32_t Ah[4], Al[4];
                    ldsm_x4(Ah, sb + SM_H1H + a);
                    ldsm_x4(Al, sb + SM_H1L + a);
                    uint32_t a0 = SWZ((uint32_t)((ks * 16 + bk) * 64 + bnb));
                    uint32_t a1 = SWZ((uint32_t)((ks * 16 + 8 + bk) * 64 + bnb));
                    uint32_t bh0[4], bh1[4], bl0[4], bl1[4];
                    ldsm_x4t(bh0, w1h + a0);
                    ldsm_x4t(bh1, w1h + a1);
                    ldsm_x4t(bl0, w1l + a0);
                    ldsm_x4t(bl1, w1l + a1);
#pragma unroll
                    for (int nb = 0; nb < 4; nb++) {
                        mma_bf16(d2[nb], Ah, bh0[nb], bh1[nb]);
                        mma_bf16(d2[nb], Al, bh0[nb], bh1[nb]);
                        mma_bf16(d2[nb], Ah, bl0[nb], bl1[nb]);
                    }
                }
            }
            {
                float* h2 = (float*)(smem + SM_H2 + br * 16384);
                int pr = wid * 16 + (lane >> 2);
#pragma unroll
                for (int nb = 0; nb < 4; nb++) {
                    int j = nb * 8 + (lane & 3) * 2;
                    float c0 = b1s[br * 32 + j], c1 = b1s[br * 32 + j + 1];
                    h2[pr * 32 + j]           = fmaxf(d2[nb][0] + c0, 0.f);
                    h2[pr * 32 + j + 1]       = fmaxf(d2[nb][1] + c1, 0.f);
                    h2[(pr + 8) * 32 + j]     = fmaxf(d2[nb][2] + c0, 0.f);
                    h2[(pr + 8) * 32 + j + 1] = fmaxf(d2[nb][3] + c1, 0.f);
                }
            }
            __syncthreads();   // H2 done; safe to overwrite H1 next branch
        }

        // ---- sorted-run segment reduction: 64 features x 4 point-chunks ----
        {
            int f = tid & 63, q = tid >> 6, fc = f & 31;
            const float* src = (const float*)(smem + SM_H2 + ((f < 32) ? 0 : 16384));
            float* dst = (f < 32) ? g_seg_t : g_seg_r;
            const int* sid = (const int*)(smem + SM_SID);
            int cur = -1; float acc = 0.f;
#pragma unroll 1
            for (int p = q * 32; p < q * 32 + 32; ++p) {
                int s = sid[p];
                if (s != cur) {
                    if (cur >= 0) atomicAdd(&dst[cur * 32 + fc], acc);
                    cur = s; acc = 0.f;
                }
                if (s >= 0) acc += src[p * 32 + fc];
            }
            if (cur >= 0) atomicAdd(&dst[cur * 32 + fc], acc);
        }
        __syncthreads();
    }
}

// ============================ head kernel ==================================
#define HS_F0   0
#define HS_C0   2048
#define HS_B0   4096
#define HS_CT1  6144
#define HS_F0B  8192
#define HS_C0B  8256
#define HS_B0B  8320
#define HS_F1   8384
#define HS_C1   8448
#define HS_B1   8512
#define HS_CT0  8576
#define HS_CT0B 8768
#define HS_CT1B 8832
#define HS_POL  8864
#define HS_SCAL 8928
#define HS_SIZE 8936

__device__ __forceinline__ void copy4h(float* dst, const float* __restrict__ src,
                                       int n, int tid) {
    for (int i = tid; i < (n >> 2); i += 256)
        reinterpret_cast<float4*>(dst)[i] =
            reinterpret_cast<const float4*>(src)[i];
}

__global__ __launch_bounds__(256)
void head_kernel(const float* __restrict__ fwd0_w, const float* __restrict__ fwd0_b,
                 const float* __restrict__ fwd1_w, const float* __restrict__ fwd1_b,
                 const float* __restrict__ com0_w, const float* __restrict__ com0_b,
                 const float* __restrict__ com1_w, const float* __restrict__ com1_b,
                 const float* __restrict__ bwd0_w, const float* __restrict__ bwd0_b,
                 const float* __restrict__ bwd1_w, const float* __restrict__ bwd1_b,
                 const float* __restrict__ cost0_w, const float* __restrict__ cost0_b,
                 const float* __restrict__ cost1_w, const float* __restrict__ cost1_b,
                 const float* __restrict__ pol_w, const float* __restrict__ pol_b,
                 float* __restrict__ out) {
    __shared__ float sw[HS_SIZE];
    int tid = threadIdx.x;
    copy4h(sw + HS_F0,   fwd0_w, 2048, tid);
    copy4h(sw + HS_C0,   com0_w, 2048, tid);
    copy4h(sw + HS_B0,   bwd0_w, 2048, tid);
    copy4h(sw + HS_CT1,  cost1_w, 2048, tid);
    copy4h(sw + HS_F0B,  fwd0_b, 64, tid);
    copy4h(sw + HS_C0B,  com0_b, 64, tid);
    copy4h(sw + HS_B0B,  bwd0_b, 64, tid);
    copy4h(sw + HS_F1,   fwd1_w, 64, tid);
    copy4h(sw + HS_C1,   com1_w, 64, tid);
    copy4h(sw + HS_B1,   bwd1_w, 64, tid);
    copy4h(sw + HS_CT0,  cost0_w, 192, tid);
    copy4h(sw + HS_CT0B, cost0_b, 64, tid);
    copy4h(sw + HS_CT1B, cost1_b, 32, tid);
    copy4h(sw + HS_POL,  pol_w, 64, tid);
    if (tid == 0) {
        sw[HS_SCAL + 0] = fwd1_b[0];
        sw[HS_SCAL + 1] = com1_b[0];
        sw[HS_SCAL + 2] = bwd1_b[0];
        sw[HS_SCAL + 3] = pol_b[0];
    }
    __syncthreads();

    int s = blockIdx.x * 256 + tid;

    float t[32], r[32];
#pragma unroll
    for (int i = 0; i < 8; i++) {
        float4 v = *reinterpret_cast<const float4*>(&g_seg_t[(size_t)s * 32 + i * 4]);
        t[i * 4] = v.x; t[i * 4 + 1] = v.y; t[i * 4 + 2] = v.z; t[i * 4 + 3] = v.w;
        float4 u = *reinterpret_cast<const float4*>(&g_seg_r[(size_t)s * 32 + i * 4]);
        r[i * 4] = u.x; r[i * 4 + 1] = u.y; r[i * 4 + 2] = u.z; r[i * 4 + 3] = u.w;
    }

    auto head = [&](const float* w0, const float* b0, const float* w1, float b1s) -> float {
        float o = b1s;
#pragma unroll
        for (int i4 = 0; i4 < 16; i4++) {
            float4 hb = *reinterpret_cast<const float4*>(&b0[i4 * 4]);
            float h0 = hb.x, h1 = hb.y, h2 = hb.z, h3 = hb.w;
#pragma unroll
            for (int k = 0; k < 32; k++) {
                float4 w = *reinterpret_cast<const float4*>(&w0[k * 64 + i4 * 4]);
                h0 = fmaf(t[k], w.x, h0); h1 = fmaf(t[k], w.y, h1);
                h2 = fmaf(t[k], w.z, h2); h3 = fmaf(t[k], w.w, h3);
            }
            float4 wv = *reinterpret_cast<const float4*>(&w1[i4 * 4]);
            o += fmaxf(h0, 0.f) * wv.x + fmaxf(h1, 0.f) * wv.y +
                 fmaxf(h2, 0.f) * wv.z + fmaxf(h3, 0.f) * wv.w;
        }
        return o;
    };

    float fc = head(sw + HS_F0, sw + HS_F0B, sw + HS_F1, sw[HS_SCAL + 0]);
    float cc = head(sw + HS_C0, sw + HS_C0B, sw + HS_C1, sw[HS_SCAL + 1]);
    float bc = head(sw + HS_B0, sw + HS_B0B, sw + HS_B1, sw[HS_SCAL + 2]);

    float c1[64];
#pragma unroll
    for (int i4 = 0; i4 < 16; i4++) {
        float4 a  = *reinterpret_cast<const float4*>(&sw[HS_CT0B + i4 * 4]);
        float4 w0 = *reinterpret_cast<const float4*>(&sw[HS_CT0 + 0 * 64 + i4 * 4]);
        float4 w1 = *reinterpret_cast<const float4*>(&sw[HS_CT0 + 1 * 64 + i4 * 4]);
        float4 w2 = *reinterpret_cast<const float4*>(&sw[HS_CT0 + 2 * 64 + i4 * 4]);
        a.x = fmaf(fc, w0.x, fmaf(cc, w1.x, fmaf(bc, w2.x, a.x)));
        a.y = fmaf(fc, w0.y, fmaf(cc, w1.y, fmaf(bc, w2.y, a.y)));
        a.z = fmaf(fc, w0.z, fmaf(cc, w1.z, fmaf(bc, w2.z, a.z)));
        a.w = fmaf(fc, w0.w, fmaf(cc, w1.w, fmaf(bc, w2.w, a.w)));
        c1[i4 * 4 + 0] = fmaxf(a.x, 0.f);
        c1[i4 * 4 + 1] = fmaxf(a.y, 0.f);
        c1[i4 * 4 + 2] = fmaxf(a.z, 0.f);
        c1[i4 * 4 + 3] = fmaxf(a.w, 0.f);
    }

    float logit = sw[HS_SCAL + 3];
#pragma unroll
    for (int k = 0; k < 32; k++) logit = fmaf(r[k], sw[HS_POL + k], logit);

#pragma unroll
    for (int j4 = 0; j4 < 8; j4++) {
        float4 a = *reinterpret_cast<const float4*>(&sw[HS_CT1B + j4 * 4]);
#pragma unroll
        for (int k = 0; k < 64; k++) {
            float4 w = *reinterpret_cast<const float4*>(&sw[HS_CT1 + k * 32 + j4 * 4]);
            a.x = fmaf(c1[k], w.x, a.x); a.y = fmaf(c1[k], w.y, a.y);
            a.z = fmaf(c1[k], w.z, a.z); a.w = fmaf(c1[k], w.w, a.w);
        }
        float4 pw = *reinterpret_cast<const float4*>(&sw[HS_POL + 32 + j4 * 4]);
        logit += fmaxf(a.x, 0.f) * pw.x + fmaxf(a.y, 0.f) * pw.y +
                 fmaxf(a.z, 0.f) * pw.z + fmaxf(a.w, 0.f) * pw.w;
    }
    out[s] = logit;
}

// ============================ launcher =====================================
extern "C" void kernel_launch(void* const* d_in, const int* in_sizes, int n_in,
                              void* d_out, int out_size) {
    int off = (in_sizes[2] == 1 && in_sizes[3] == 1) ? 4 : 2;
    const float* x   = (const float*)d_in[0];
    const int*   seg = (const int*)d_in[1];
    const float* tfc0_w = (const float*)d_in[off + 0];
    const float* tfc0_b = (const float*)d_in[off + 1];
    const float* tfc1_w = (const float*)d_in[off + 2];
    const float* tfc1_b = (const float*)d_in[off + 3];
    const float* fwd0_w = (const float*)d_in[off + 4];
    const float* fwd0_b = (const float*)d_in[off + 5];
    const float* fwd1_w = (const float*)d_in[off + 6];
    const float* fwd1_b = (const float*)d_in[off + 7];
    const float* com0_w = (const float*)d_in[off + 8];
    const float* com0_b = (const float*)d_in[off + 9];
    const float* com1_w = (const float*)d_in[off + 10];
    const float* com1_b = (const float*)d_in[off + 11];
    const float* bwd0_w = (const float*)d_in[off + 12];
    const float* bwd0_b = (const float*)d_in[off + 13];
    const float* bwd1_w = (const float*)d_in[off + 14];
    const float* bwd1_b = (const float*)d_in[off + 15];
    const float* rl0_w  = (const float*)d_in[off + 16];
    const float* rl0_b  = (const float*)d_in[off + 17];
    const float* rl1_w  = (const float*)d_in[off + 18];
    const float* rl1_b  = (const float*)d_in[off + 19];
    const float* cost0_w = (const float*)d_in[off + 20];
    const float* cost0_b = (const float*)d_in[off + 21];
    const float* cost1_w = (const float*)d_in[off + 22];
    const float* cost1_b = (const float*)d_in[off + 23];
    const float* pol_w   = (const float*)d_in[off + 24];
    const float* pol_b   = (const float*)d_in[off + 25];

    int N = in_sizes[0] / FDIM;

    cudaFuncSetAttribute(mlp_mma_kernel,
                         cudaFuncAttributeMaxDynamicSharedMemorySize, SMEM_BYTES);

    zero_seg_kernel<<<(SSEG * 32 + 255) / 256, 256>>>();
    prep_kernel<<<1, NTHREADS>>>(tfc0_w, tfc1_w, rl0_w, rl1_w);

    mlp_mma_kernel<<<GRID_MAIN, NTHREADS, SMEM_BYTES>>>(
        x, seg, tfc0_b, rl0_b, tfc1_b, rl1_b, N);

    head_kernel<<<SSEG / 256, 256>>>(
        fwd0_w, fwd0_b, fwd1_w, fwd1_b,
        com0_w, com0_b, com1_w, com1_b,
        bwd0_w, bwd0_b, bwd1_w, bwd1_b,
        cost0_w, cost0_b, cost1_w, cost1_b,
        pol_w, pol_b, (float*)d_out);
}

// round 11
// speedup vs baseline: 3.2949x; 1.4106x over previous
#include <cuda_runtime.h>
#include <cstdint>

// ============================ problem constants ============================
#define TILE_P 128
#define SSEG   16384          // B*D = 256*64
#define FDIM   64
#define NTHREADS 256
#define GRID_MAIN 148

// ============================ scratch globals ==============================
__device__ __align__(16) float g_seg_t[SSEG * 32];
__device__ __align__(16) float g_seg_r[SSEG * 32];

// ============================ smem layout (bytes) ==========================
// X:   [128 p][68 f32]  (row stride 272B, 64 used)  -> 34816
// H1:  [128 p][132 f32] (row stride 528B, 128 used) -> 67584
// W1P: 2 br x [32 n][136 f32] pair-packed           -> 34816
// H2:  2 br x [128 p][32 f32]                       -> 32768
#define SM_X    0
#define SM_H1   34816
#define SM_W1P  102400
#define SM_H2   137216
#define SM_SID  169984
#define SM_B0   170496
#define SM_B1   171520
#define SMEM_BYTES 171776

#define XSTRIDE  68
#define H1STRIDE 132
#define W1STRIDE 136

// ============================ PTX helpers ==================================
__device__ __forceinline__ uint32_t smem_u32(const void* p) {
    uint32_t a;
    asm("{ .reg .u64 t; cvta.to.shared.u64 t, %1; cvt.u32.u64 %0, t; }"
        : "=r"(a) : "l"(p));
    return a;
}
__device__ __forceinline__ void ldsm_x4(uint32_t* r, uint32_t a) {
    asm volatile("ldmatrix.sync.aligned.m8n8.x4.shared.b16 {%0,%1,%2,%3}, [%4];"
                 : "=r"(r[0]), "=r"(r[1]), "=r"(r[2]), "=r"(r[3]) : "r"(a));
}
__device__ __forceinline__ void mma_tf32(float* d, const uint32_t* a,
                                         uint32_t b0, uint32_t b1) {
    asm volatile(
        "mma.sync.aligned.m16n8k8.row.col.f32.tf32.tf32.f32 "
        "{%0,%1,%2,%3}, {%4,%5,%6,%7}, {%8,%9}, {%0,%1,%2,%3};"
        : "+f"(d[0]), "+f"(d[1]), "+f"(d[2]), "+f"(d[3])
        : "r"(a[0]), "r"(a[1]), "r"(a[2]), "r"(a[3]), "r"(b0), "r"(b1));
}
__device__ __forceinline__ uint32_t f2tf(float v) {
    uint32_t r;
    asm("cvt.rna.tf32.f32 %0, %1;" : "=r"(r) : "f"(v));
    return r;
}

// ============================ small kernels ================================
__global__ void zero_seg_kernel() {
    int i = blockIdx.x * blockDim.x + threadIdx.x;
    if (i < SSEG * 32) { g_seg_t[i] = 0.f; g_seg_r[i] = 0.f; }
}

// ============================ main persistent kernel =======================
__global__ __launch_bounds__(NTHREADS, 1)
void mlp_mma_kernel(const float* __restrict__ x, const int* __restrict__ seg,
                    const float* __restrict__ w0t, const float* __restrict__ w0r,
                    const float* __restrict__ w1t, const float* __restrict__ w1r,
                    const float* __restrict__ b0t, const float* __restrict__ b0r,
                    const float* __restrict__ b1t, const float* __restrict__ b1r,
                    int N) {
    extern __shared__ char smem[];
    uint32_t sb = smem_u32(smem);
    int tid = threadIdx.x, lane = tid & 31, wid = tid >> 5;

    // ---- GEMM1 B fragments persistent in regs (tf32, once from global) ----
    // warp owns 16 N-cols [wid*16, wid*16+16): nb in {0,1}
    uint32_t B1r[2][8][2][2];
    {
#pragma unroll
        for (int br = 0; br < 2; br++) {
            const float* w0 = br ? w0r : w0t;
#pragma unroll
            for (int ks = 0; ks < 8; ks++)
#pragma unroll
                for (int nb = 0; nb < 2; nb++) {
                    int kg = ks * 8 + (lane & 3);
                    int ng = wid * 16 + nb * 8 + (lane >> 2);
                    B1r[br][ks][nb][0] = f2tf(w0[kg * 128 + ng]);
                    B1r[br][ks][nb][1] = f2tf(w0[(kg + 4) * 128 + ng]);
                }
        }
    }

    // ---- build W1P (pair-packed tf32) + biases in smem ----
    {
#pragma unroll
        for (int br = 0; br < 2; br++) {
            uint32_t* dst = (uint32_t*)(smem + SM_W1P + br * 17408);
            const float* w1 = br ? w1r : w1t;
            for (int i = tid; i < 4096; i += NTHREADS) {
                int k = i >> 5, n = i & 31;
                int ks = k >> 3, km = k & 3, h = (k >> 2) & 1;
                dst[n * W1STRIDE + ks * 8 + km * 2 + h] = f2tf(w1[k * 32 + n]);
            }
        }
        float* b0s = (float*)(smem + SM_B0);
        float* b1s = (float*)(smem + SM_B1);
        if (tid < 128) { b0s[tid] = b0t[tid]; b0s[128 + tid] = b0r[tid]; }
        if (tid < 32)  { b1s[tid] = b1t[tid]; b1s[32 + tid]  = b1r[tid]; }
    }

    const float* b0s = (const float*)(smem + SM_B0);
    const float* b1s = (const float*)(smem + SM_B1);

    int T = (N + TILE_P - 1) / TILE_P;
    int tile = blockIdx.x;
    if (tile >= T) return;

    // ---- register prefetch of first tile ----
    float4 xr[8];
    int sidr = -1;
    {
        int p0 = tile * TILE_P;
        const float4* x4 = reinterpret_cast<const float4*>(x);
#pragma unroll
        for (int it = 0; it < 8; it++) {
            int idx = tid + it * NTHREADS;
            int p = idx >> 4, c4 = idx & 15;
            xr[it] = (p0 + p < N) ? x4[(size_t)(p0 + p) * 16 + c4]
                                  : make_float4(0.f, 0.f, 0.f, 0.f);
        }
        if (tid < TILE_P) sidr = (p0 + tid < N) ? seg[p0 + tid] : -1;
    }
    __syncthreads();   // W1P / biases ready

    // ldmatrix lane-address components (row, 16B-chunk select)
    const int am = (lane & 7) + ((lane >> 3) & 1) * 8;
    const int ak = (lane >> 4) * 16;

    for (; tile < T; tile += GRID_MAIN) {
        // ---- store prefetched x tile (tf32-rounded) + sid ----
#pragma unroll
        for (int it = 0; it < 8; it++) {
            int idx = tid + it * NTHREADS;
            int p = idx >> 4, c4 = idx & 15;
            float4 v = xr[it];
            uint4 o = make_uint4(f2tf(v.x), f2tf(v.y), f2tf(v.z), f2tf(v.w));
            *(uint4*)(smem + SM_X + (p * XSTRIDE + c4 * 4) * 4) = o;
        }
        if (tid < TILE_P) ((int*)(smem + SM_SID))[tid] = sidr;
        __syncthreads();

        // ---- prefetch next tile into regs (overlaps compute) ----
        int nt = tile + GRID_MAIN;
        if (nt < T) {
            int p0 = nt * TILE_P;
            const float4* x4 = reinterpret_cast<const float4*>(x);
#pragma unroll
            for (int it = 0; it < 8; it++) {
                int idx = tid + it * NTHREADS;
                int p = idx >> 4, c4 = idx & 15;
                xr[it] = (p0 + p < N) ? x4[(size_t)(p0 + p) * 16 + c4]
                                      : make_float4(0.f, 0.f, 0.f, 0.f);
            }
            if (tid < TILE_P) sidr = (p0 + tid < N) ? seg[p0 + tid] : -1;
        }

#pragma unroll
        for (int br = 0; br < 2; br++) {
            // ============ GEMM1: X[128x64] @ W0 -> relu -> H1 (tf32) ========
#pragma unroll 1
            for (int mb = 0; mb < 8; mb++) {
                uint32_t A[8][4];
#pragma unroll
                for (int ks = 0; ks < 8; ks++)
                    ldsm_x4(A[ks], sb + SM_X + (mb * 16 + am) * 272 + ks * 32 + ak);
                float d[2][4] = {{0.f, 0.f, 0.f, 0.f}, {0.f, 0.f, 0.f, 0.f}};
#pragma unroll
                for (int ks = 0; ks < 8; ks++)
#pragma unroll
                    for (int nb = 0; nb < 2; nb++)
                        mma_tf32(d[nb], A[ks], B1r[br][ks][nb][0], B1r[br][ks][nb][1]);
                // epilogue: bias + relu + tf32-round -> H1
                int pr = mb * 16 + (lane >> 2);
#pragma unroll
                for (int nb = 0; nb < 2; nb++) {
                    int j0 = wid * 16 + nb * 8 + (lane & 3) * 2;
                    float c0 = b0s[br * 128 + j0], c1 = b0s[br * 128 + j0 + 1];
                    uint2 o0 = make_uint2(f2tf(fmaxf(d[nb][0] + c0, 0.f)),
                                          f2tf(fmaxf(d[nb][1] + c1, 0.f)));
                    *(uint2*)(smem + SM_H1 + (pr * H1STRIDE + j0) * 4) = o0;
                    uint2 o1 = make_uint2(f2tf(fmaxf(d[nb][2] + c0, 0.f)),
                                          f2tf(fmaxf(d[nb][3] + c1, 0.f)));
                    *(uint2*)(smem + SM_H1 + ((pr + 8) * H1STRIDE + j0) * 4) = o1;
                }
            }
            __syncthreads();

            // ============ GEMM2: H1[128x128] @ W1 -> relu -> H2 =============
            // warp owns 16 rows (mb = wid), all 32 cols
            float d2[4][4] = {{0.f, 0.f, 0.f, 0.f}, {0.f, 0.f, 0.f, 0.f},
                              {0.f, 0.f, 0.f, 0.f}, {0.f, 0.f, 0.f, 0.f}};
            {
                // generic pointer base for C++ derefs (NOT the cvta.to.shared int)
                const char* w1pg = smem + SM_W1P + br * 17408;
#pragma unroll 1
                for (int ks = 0; ks < 16; ks++) {
                    uint32_t A2[4];
                    ldsm_x4(A2, sb + SM_H1 + (wid * 16 + am) * 528 + ks * 32 + ak);
#pragma unroll
                    for (int nb = 0; nb < 4; nb++) {
                        int n = nb * 8 + (lane >> 2);
                        uint2 b = *(const uint2*)(w1pg +
                            (n * W1STRIDE + ks * 8 + (lane & 3) * 2) * 4);
                        mma_tf32(d2[nb], A2, b.x, b.y);
                    }
                }
            }
            {
                float* h2 = (float*)(smem + SM_H2 + br * 16384);
                int pr = wid * 16 + (lane >> 2);
#pragma unroll
                for (int nb = 0; nb < 4; nb++) {
                    int j = nb * 8 + (lane & 3) * 2;
                    float c0 = b1s[br * 32 + j], c1 = b1s[br * 32 + j + 1];
                    h2[pr * 32 + j]           = fmaxf(d2[nb][0] + c0, 0.f);
                    h2[pr * 32 + j + 1]       = fmaxf(d2[nb][1] + c1, 0.f);
                    h2[(pr + 8) * 32 + j]     = fmaxf(d2[nb][2] + c0, 0.f);
                    h2[(pr + 8) * 32 + j + 1] = fmaxf(d2[nb][3] + c1, 0.f);
                }
            }
            __syncthreads();   // H2[br] done; H1 free for next branch
        }

        // ---- sorted-run segment reduction: 64 features x 4 point-chunks ----
        {
            int f = tid & 63, q = tid >> 6, fc = f & 31;
            const float* src = (const float*)(smem + SM_H2 + ((f < 32) ? 0 : 16384));
            float* dst = (f < 32) ? g_seg_t : g_seg_r;
            const int* sid = (const int*)(smem + SM_SID);
            int cur = -1; float acc = 0.f;
#pragma unroll 1
            for (int p = q * 32; p < q * 32 + 32; ++p) {
                int s = sid[p];
                if (s != cur) {
                    if (cur >= 0) atomicAdd(&dst[cur * 32 + fc], acc);
                    cur = s; acc = 0.f;
                }
                if (s >= 0) acc += src[p * 32 + fc];
            }
            if (cur >= 0) atomicAdd(&dst[cur * 32 + fc], acc);
        }
        __syncthreads();
    }
}

// ============================ head kernel (2 threads/segment) ==============
#define HS_F0   0
#define HS_C0   2048
#define HS_B0   4096
#define HS_CT1  6144
#define HS_F0B  8192
#define HS_C0B  8256
#define HS_B0B  8320
#define HS_F1   8384
#define HS_C1   8448
#define HS_B1   8512
#define HS_CT0  8576
#define HS_CT0B 8768
#define HS_CT1B 8832
#define HS_POL  8864
#define HS_SCAL 8928
#define HS_SIZE 8936

__device__ __forceinline__ void copy4h(float* dst, const float* __restrict__ src,
                                       int n, int tid) {
    for (int i = tid; i < (n >> 2); i += 256)
        reinterpret_cast<float4*>(dst)[i] =
            reinterpret_cast<const float4*>(src)[i];
}

__global__ __launch_bounds__(256)
void head_kernel(const float* __restrict__ fwd0_w, const float* __restrict__ fwd0_b,
                 const float* __restrict__ fwd1_w, const float* __restrict__ fwd1_b,
                 const float* __restrict__ com0_w, const float* __restrict__ com0_b,
                 const float* __restrict__ com1_w, const float* __restrict__ com1_b,
                 const float* __restrict__ bwd0_w, const float* __restrict__ bwd0_b,
                 const float* __restrict__ bwd1_w, const float* __restrict__ bwd1_b,
                 const float* __restrict__ cost0_w, const float* __restrict__ cost0_b,
                 const float* __restrict__ cost1_w, const float* __restrict__ cost1_b,
                 const float* __restrict__ pol_w, const float* __restrict__ pol_b,
                 float* __restrict__ out) {
    __shared__ __align__(16) float sw[HS_SIZE];
    int tid = threadIdx.x;
    copy4h(sw + HS_F0,   fwd0_w, 2048, tid);
    copy4h(sw + HS_C0,   com0_w, 2048, tid);
    copy4h(sw + HS_B0,   bwd0_w, 2048, tid);
    copy4h(sw + HS_CT1,  cost1_w, 2048, tid);
    copy4h(sw + HS_F0B,  fwd0_b, 64, tid);
    copy4h(sw + HS_C0B,  com0_b, 64, tid);
    copy4h(sw + HS_B0B,  bwd0_b, 64, tid);
    copy4h(sw + HS_F1,   fwd1_w, 64, tid);
    copy4h(sw + HS_C1,   com1_w, 64, tid);
    copy4h(sw + HS_B1,   bwd1_w, 64, tid);
    copy4h(sw + HS_CT0,  cost0_w, 192, tid);
    copy4h(sw + HS_CT0B, cost0_b, 64, tid);
    copy4h(sw + HS_CT1B, cost1_b, 32, tid);
    copy4h(sw + HS_POL,  pol_w, 64, tid);
    if (tid == 0) {
        sw[HS_SCAL + 0] = fwd1_b[0];
        sw[HS_SCAL + 1] = com1_b[0];
        sw[HS_SCAL + 2] = bwd1_b[0];
        sw[HS_SCAL + 3] = pol_b[0];
    }
    __syncthreads();

    int idx = blockIdx.x * 256 + tid;       // 0 .. 2*SSEG-1
    int s = idx >> 1, half = idx & 1;       // 2 threads per segment

    float t[32], r[32];
#pragma unroll
    for (int i = 0; i < 8; i++) {
        float4 v = *reinterpret_cast<const float4*>(&g_seg_t[(size_t)s * 32 + i * 4]);
        t[i * 4] = v.x; t[i * 4 + 1] = v.y; t[i * 4 + 2] = v.z; t[i * 4 + 3] = v.w;
        float4 u = *reinterpret_cast<const float4*>(&g_seg_r[(size_t)s * 32 + i * 4]);
        r[i * 4] = u.x; r[i * 4 + 1] = u.y; r[i * 4 + 2] = u.z; r[i * 4 + 3] = u.w;
    }

    // half of each head's 64 hidden units
    auto headp = [&](const float* w0, const float* b0, const float* w1) -> float {
        float o = 0.f;
#pragma unroll
        for (int q = 0; q < 8; q++) {
            int i4 = half * 8 + q;
            float4 hb = *reinterpret_cast<const float4*>(&b0[i4 * 4]);
            float h0 = hb.x, h1 = hb.y, h2 = hb.z, h3 = hb.w;
#pragma unroll
            for (int k = 0; k < 32; k++) {
                float4 w = *reinterpret_cast<const float4*>(&w0[k * 64 + i4 * 4]);
                h0 = fmaf(t[k], w.x, h0); h1 = fmaf(t[k], w.y, h1);
                h2 = fmaf(t[k], w.z, h2); h3 = fmaf(t[k], w.w, h3);
            }
            float4 wv = *reinterpret_cast<const float4*>(&w1[i4 * 4]);
            o += fmaxf(h0, 0.f) * wv.x + fmaxf(h1, 0.f) * wv.y +
                 fmaxf(h2, 0.f) * wv.z + fmaxf(h3, 0.f) * wv.w;
        }
        return o;
    };

    float fc = headp(sw + HS_F0, sw + HS_F0B, sw + HS_F1);
    float cc = headp(sw + HS_C0, sw + HS_C0B, sw + HS_C1);
    float bc = headp(sw + HS_B0, sw + HS_B0B, sw + HS_B1);
    fc += __shfl_xor_sync(0xFFFFFFFFu, fc, 1); fc += sw[HS_SCAL + 0];
    cc += __shfl_xor_sync(0xFFFFFFFFu, cc, 1); cc += sw[HS_SCAL + 1];
    bc += __shfl_xor_sync(0xFFFFFFFFu, bc, 1); bc += sw[HS_SCAL + 2];

    // cost MLP layer 1: this thread's 32 of 64 hidden units
    float c1h[32];
#pragma unroll
    for (int q = 0; q < 8; q++) {
        int i4 = half * 8 + q;
        float4 a  = *reinterpret_cast<const float4*>(&sw[HS_CT0B + i4 * 4]);
        float4 w0 = *reinterpret_cast<const float4*>(&sw[HS_CT0 + 0 * 64 + i4 * 4]);
        float4 w1 = *reinterpret_cast<const float4*>(&sw[HS_CT0 + 1 * 64 + i4 * 4]);
        float4 w2 = *reinterpret_cast<const float4*>(&sw[HS_CT0 + 2 * 64 + i4 * 4]);
        a.x = fmaf(fc, w0.x, fmaf(cc, w1.x, fmaf(bc, w2.x, a.x)));
        a.y = fmaf(fc, w0.y, fmaf(cc, w1.y, fmaf(bc, w2.y, a.y)));
        a.z = fmaf(fc, w0.z, fmaf(cc, w1.z, fmaf(bc, w2.z, a.z)));
        a.w = fmaf(fc, w0.w, fmaf(cc, w1.w, fmaf(bc, w2.w, a.w)));
        c1h[q * 4 + 0] = fmaxf(a.x, 0.f);
        c1h[q * 4 + 1] = fmaxf(a.y, 0.f);
        c1h[q * 4 + 2] = fmaxf(a.z, 0.f);
        c1h[q * 4 + 3] = fmaxf(a.w, 0.f);
    }

    // cost layer 2 partials over this thread's k-half, all 32 outputs
    float pj[32];
#pragma unroll
    for (int j = 0; j < 32; j++) pj[j] = 0.f;
#pragma unroll
    for (int k = 0; k < 32; k++) {
        int kg = half * 32 + k;
        const float* wr = &sw[HS_CT1 + kg * 32];
#pragma unroll
        for (int j = 0; j < 32; j++) pj[j] = fmaf(c1h[k], wr[j], pj[j]);
    }
#pragma unroll
    for (int j = 0; j < 32; j++)
        pj[j] += __shfl_xor_sync(0xFFFFFFFFu, pj[j], 1);

    // policy dot: split r-part and c-part by half
    float logit = 0.f;
#pragma unroll
    for (int k = 0; k < 16; k++) {
        int kg = half * 16 + k;
        logit = fmaf(r[kg], sw[HS_POL + kg], logit);
    }
#pragma unroll
    for (int j = 0; j < 16; j++) {
        int jg = half * 16 + j;
        float v = fmaxf(pj[jg] + sw[HS_CT1B + jg], 0.f);
        logit = fmaf(v, sw[HS_POL + 32 + jg], logit);
    }
    logit += __shfl_xor_sync(0xFFFFFFFFu, logit, 1);
    if (half == 0) out[s] = logit + sw[HS_SCAL + 3];
}

// ============================ launcher =====================================
extern "C" void kernel_launch(void* const* d_in, const int* in_sizes, int n_in,
                              void* d_out, int out_size) {
    int off = (in_sizes[2] == 1 && in_sizes[3] == 1) ? 4 : 2;
    const float* x   = (const float*)d_in[0];
    const int*   seg = (const int*)d_in[1];
    const float* tfc0_w = (const float*)d_in[off + 0];
    const float* tfc0_b = (const float*)d_in[off + 1];
    const float* tfc1_w = (const float*)d_in[off + 2];
    const float* tfc1_b = (const float*)d_in[off + 3];
    const float* fwd0_w = (const float*)d_in[off + 4];
    const float* fwd0_b = (const float*)d_in[off + 5];
    const float* fwd1_w = (const float*)d_in[off + 6];
    const float* fwd1_b = (const float*)d_in[off + 7];
    const float* com0_w = (const float*)d_in[off + 8];
    const float* com0_b = (const float*)d_in[off + 9];
    const float* com1_w = (const float*)d_in[off + 10];
    const float* com1_b = (const float*)d_in[off + 11];
    const float* bwd0_w = (const float*)d_in[off + 12];
    const float* bwd0_b = (const float*)d_in[off + 13];
    const float* bwd1_w = (const float*)d_in[off + 14];
    const float* bwd1_b = (const float*)d_in[off + 15];
    const float* rl0_w  = (const float*)d_in[off + 16];
    const float* rl0_b  = (const float*)d_in[off + 17];
    const float* rl1_w  = (const float*)d_in[off + 18];
    const float* rl1_b  = (const float*)d_in[off + 19];
    const float* cost0_w = (const float*)d_in[off + 20];
    const float* cost0_b = (const float*)d_in[off + 21];
    const float* cost1_w = (const float*)d_in[off + 22];
    const float* cost1_b = (const float*)d_in[off + 23];
    const float* pol_w   = (const float*)d_in[off + 24];
    const float* pol_b   = (const float*)d_in[off + 25];

    int N = in_sizes[0] / FDIM;

    cudaFuncSetAttribute(mlp_mma_kernel,
                         cudaFuncAttributeMaxDynamicSharedMemorySize, SMEM_BYTES);

    zero_seg_kernel<<<(SSEG * 32 + 255) / 256, 256>>>();

    mlp_mma_kernel<<<GRID_MAIN, NTHREADS, SMEM_BYTES>>>(
        x, seg, tfc0_w, rl0_w, tfc1_w, rl1_w,
        tfc0_b, rl0_b, tfc1_b, rl1_b, N);

    head_kernel<<<(2 * SSEG) / 256, 256>>>(
        fwd0_w, fwd0_b, fwd1_w, fwd1_b,
        com0_w, com0_b, com1_w, com1_b,
        bwd0_w, bwd0_b, bwd1_w, bwd1_b,
        cost0_w, cost0_b, cost1_w, cost1_b,
        pol_w, pol_b, (float*)d_out);
}